// round 1
// baseline (speedup 1.0000x reference)
#include <cuda_runtime.h>
#include <math.h>

#define N_NODES 100000
#define N_EDGES 1600000
#define N_GRAPHS 64
#define D 128

// ---------------- scratch (no allocations allowed) ----------------
__device__ float g_bufA[N_NODES * D];   // GEMM output / spmm input
__device__ float g_bufB[N_NODES * D];   // spmm output / GEMM input
__device__ float g_norm_src[N_NODES];
__device__ float g_norm_dst[N_NODES];
__device__ int   g_indeg[N_NODES];
__device__ int   g_outdeg[N_NODES];
__device__ int   g_rowstart[N_NODES];
__device__ int   g_cursor[N_NODES];
__device__ int   g_col[N_EDGES];
__device__ float g_gsum[N_GRAPHS * D];
__device__ int   g_gcnt[N_GRAPHS];
__device__ int   g_ctr;

// ---------------- init ----------------
__global__ void k_zero() {
    int i = blockIdx.x * blockDim.x + threadIdx.x;
    int stride = gridDim.x * blockDim.x;
    for (int j = i; j < N_NODES; j += stride) {
        g_indeg[j] = 0; g_outdeg[j] = 0; g_cursor[j] = 0;
    }
    for (int j = i; j < N_GRAPHS * D; j += stride) g_gsum[j] = 0.f;
    if (i < N_GRAPHS) g_gcnt[i] = 0;
    if (i == 0) g_ctr = 0;
}

__global__ void k_deg(const int* __restrict__ src, const int* __restrict__ dst) {
    int e = blockIdx.x * blockDim.x + threadIdx.x;
    if (e >= N_EDGES) return;
    atomicAdd(&g_outdeg[src[e]], 1);
    atomicAdd(&g_indeg[dst[e]], 1);
}

// norms + CSR row-start reservation (order-free: rows get arbitrary but
// disjoint contiguous regions -> no prefix scan needed)
__global__ void k_norm() {
    int i = blockIdx.x * blockDim.x + threadIdx.x;
    if (i >= N_NODES) return;
    int od = g_outdeg[i], id = g_indeg[i];
    g_norm_src[i] = rsqrtf((float)(od > 1 ? od : 1));
    g_norm_dst[i] = rsqrtf((float)(id > 1 ? id : 1));
    g_rowstart[i] = atomicAdd(&g_ctr, id);
}

__global__ void k_fill(const int* __restrict__ src, const int* __restrict__ dst) {
    int e = blockIdx.x * blockDim.x + threadIdx.x;
    if (e >= N_EDGES) return;
    int d = dst[e];
    int pos = atomicAdd(&g_cursor[d], 1);
    g_col[g_rowstart[d] + pos] = src[e];
}

// ---------------- SpMM: agg[i] = norm_dst[i] * sum_{e in row i} norm_src[s]*h[s]
// warp per destination row, thread = 4 features (float4), no atomics.
__global__ __launch_bounds__(256) void k_spmm(const float* __restrict__ ext, int first) {
    int gt = blockIdx.x * blockDim.x + threadIdx.x;
    int node = gt >> 5;
    int lane = gt & 31;
    if (node >= N_NODES) return;

    const float* hin = first ? ext : (const float*)g_bufA;
    const float4* __restrict__ h4 = (const float4*)hin;

    const int start = g_rowstart[node];
    const int deg   = g_indeg[node];

    float ax = 0.f, ay = 0.f, az = 0.f, aw = 0.f;
    int e = 0;
    for (; e + 4 <= deg; e += 4) {
        int s0 = g_col[start + e + 0];
        int s1 = g_col[start + e + 1];
        int s2 = g_col[start + e + 2];
        int s3 = g_col[start + e + 3];
        float c0 = g_norm_src[s0];
        float c1 = g_norm_src[s1];
        float c2 = g_norm_src[s2];
        float c3 = g_norm_src[s3];
        float4 v0 = h4[(size_t)s0 * 32 + lane];
        float4 v1 = h4[(size_t)s1 * 32 + lane];
        float4 v2 = h4[(size_t)s2 * 32 + lane];
        float4 v3 = h4[(size_t)s3 * 32 + lane];
        ax = fmaf(c0, v0.x, ax); ay = fmaf(c0, v0.y, ay);
        az = fmaf(c0, v0.z, az); aw = fmaf(c0, v0.w, aw);
        ax = fmaf(c1, v1.x, ax); ay = fmaf(c1, v1.y, ay);
        az = fmaf(c1, v1.z, az); aw = fmaf(c1, v1.w, aw);
        ax = fmaf(c2, v2.x, ax); ay = fmaf(c2, v2.y, ay);
        az = fmaf(c2, v2.z, az); aw = fmaf(c2, v2.w, aw);
        ax = fmaf(c3, v3.x, ax); ay = fmaf(c3, v3.y, ay);
        az = fmaf(c3, v3.z, az); aw = fmaf(c3, v3.w, aw);
    }
    for (; e < deg; e++) {
        int s = g_col[start + e];
        float c = g_norm_src[s];
        float4 v = h4[(size_t)s * 32 + lane];
        ax = fmaf(c, v.x, ax); ay = fmaf(c, v.y, ay);
        az = fmaf(c, v.z, az); aw = fmaf(c, v.w, aw);
    }
    float nd = g_norm_dst[node];
    float4 o;
    o.x = ax * nd; o.y = ay * nd; o.z = az * nd; o.w = aw * nd;
    ((float4*)g_bufB)[(size_t)node * 32 + lane] = o;
}

// ---------------- GEMM: g_bufA = g_bufB @ W + b   (100000 x 128 x 128)
// 256 threads, 32 rows x 128 cols per block. Thread = 4 rows x 4 cols.
#define GEMM_ROWS 32
#define GEMM_SMEM ((D * D + GEMM_ROWS * D) * (int)sizeof(float))  // 81920 B

__global__ __launch_bounds__(256) void k_gemm(const float* __restrict__ W,
                                              const float* __restrict__ bias) {
    extern __shared__ float sm[];
    float* Ws = sm;              // 128*128
    float* As = sm + D * D;      // 32*128
    int tid = threadIdx.x;

    const float4* W4 = (const float4*)W;
    float4* Ws4 = (float4*)Ws;
#pragma unroll
    for (int i = 0; i < (D * D / 4) / 256; i++)      // 16
        Ws4[tid + i * 256] = W4[tid + i * 256];

    int row0 = blockIdx.x * GEMM_ROWS;
    const float4* A4 = (const float4*)((const float*)g_bufB + (size_t)row0 * D);
    float4* As4 = (float4*)As;
#pragma unroll
    for (int i = 0; i < (GEMM_ROWS * D / 4) / 256; i++)  // 4
        As4[tid + i * 256] = A4[tid + i * 256];
    __syncthreads();

    int tx = tid & 31;           // 4 cols: 4*tx .. 4*tx+3
    int ty = tid >> 5;           // 4 rows: 4*ty .. 4*ty+3
    float4 bj = ((const float4*)bias)[tx];
    float4 acc0 = bj, acc1 = bj, acc2 = bj, acc3 = bj;

    const float* a0p = As + (ty * 4 + 0) * D;
    const float* a1p = As + (ty * 4 + 1) * D;
    const float* a2p = As + (ty * 4 + 2) * D;
    const float* a3p = As + (ty * 4 + 3) * D;

#pragma unroll 16
    for (int k = 0; k < D; k++) {
        float4 w = *(const float4*)(Ws + k * D + tx * 4);
        float a0 = a0p[k], a1 = a1p[k], a2 = a2p[k], a3 = a3p[k];
        acc0.x = fmaf(a0, w.x, acc0.x); acc0.y = fmaf(a0, w.y, acc0.y);
        acc0.z = fmaf(a0, w.z, acc0.z); acc0.w = fmaf(a0, w.w, acc0.w);
        acc1.x = fmaf(a1, w.x, acc1.x); acc1.y = fmaf(a1, w.y, acc1.y);
        acc1.z = fmaf(a1, w.z, acc1.z); acc1.w = fmaf(a1, w.w, acc1.w);
        acc2.x = fmaf(a2, w.x, acc2.x); acc2.y = fmaf(a2, w.y, acc2.y);
        acc2.z = fmaf(a2, w.z, acc2.z); acc2.w = fmaf(a2, w.w, acc2.w);
        acc3.x = fmaf(a3, w.x, acc3.x); acc3.y = fmaf(a3, w.y, acc3.y);
        acc3.z = fmaf(a3, w.z, acc3.z); acc3.w = fmaf(a3, w.w, acc3.w);
    }

    float* outp = g_bufA + (size_t)(row0 + ty * 4) * D;
    ((float4*)(outp + 0 * D))[tx] = acc0;
    ((float4*)(outp + 1 * D))[tx] = acc1;
    ((float4*)(outp + 2 * D))[tx] = acc2;
    ((float4*)(outp + 3 * D))[tx] = acc3;
}

// ---------------- mean-pool (graph_ids sorted -> segmented run-length reduce)
#define POOL_NODES 256
__global__ __launch_bounds__(128) void k_pool(const int* __restrict__ gid) {
    __shared__ int sg[POOL_NODES];
    int base = blockIdx.x * POOL_NODES;
    int tid = threadIdx.x;   // feature index, 128 threads
    for (int i = tid; i < POOL_NODES; i += 128) {
        int n = base + i;
        sg[i] = (n < N_NODES) ? gid[n] : -1;
    }
    __syncthreads();
    int nn = N_NODES - base; if (nn > POOL_NODES) nn = POOL_NODES;
    const float* h = (const float*)g_bufA;

    float acc = 0.f;
    int cur = sg[0];
    int run = 0;
    for (int i = 0; i < nn; i++) {
        int g = sg[i];
        if (g != cur) {
            atomicAdd(&g_gsum[cur * D + tid], acc);
            if (tid == 0) atomicAdd(&g_gcnt[cur], run);
            acc = 0.f; run = 0; cur = g;
        }
        acc += h[(size_t)(base + i) * D + tid];
        run++;
    }
    atomicAdd(&g_gsum[cur * D + tid], acc);
    if (tid == 0) atomicAdd(&g_gcnt[cur], run);
}

// ---------------- head: sigmoid(mean @ fc_w^T + fc_b)
__global__ __launch_bounds__(128) void k_final(const float* __restrict__ fcw,
                                               const float* __restrict__ fcb,
                                               float* __restrict__ out) {
    __shared__ float red[128];
    int g = blockIdx.x;
    int tid = threadIdx.x;
    red[tid] = g_gsum[g * D + tid] * fcw[tid];
    __syncthreads();
#pragma unroll
    for (int s = 64; s > 0; s >>= 1) {
        if (tid < s) red[tid] += red[tid + s];
        __syncthreads();
    }
    if (tid == 0) {
        int c = g_gcnt[g]; if (c < 1) c = 1;
        float x = red[0] / (float)c + fcb[0];
        out[g] = 1.f / (1.f + expf(-x));
    }
}

// ---------------- launch ----------------
extern "C" void kernel_launch(void* const* d_in, const int* in_sizes, int n_in,
                              void* d_out, int out_size) {
    const float* h    = (const float*)d_in[0];
    const int*   src  = (const int*)  d_in[1];
    const int*   dst  = (const int*)  d_in[2];
    const int*   gid  = (const int*)  d_in[3];
    const float* W[5] = {(const float*)d_in[4],  (const float*)d_in[6],
                         (const float*)d_in[8],  (const float*)d_in[10],
                         (const float*)d_in[12]};
    const float* b[5] = {(const float*)d_in[5],  (const float*)d_in[7],
                         (const float*)d_in[9],  (const float*)d_in[11],
                         (const float*)d_in[13]};
    const float* fcw  = (const float*)d_in[14];
    const float* fcb  = (const float*)d_in[15];
    float* out = (float*)d_out;

    cudaFuncSetAttribute(k_gemm, cudaFuncAttributeMaxDynamicSharedMemorySize, GEMM_SMEM);

    k_zero<<<256, 256>>>();
    k_deg <<<(N_EDGES + 255) / 256, 256>>>(src, dst);
    k_norm<<<(N_NODES + 255) / 256, 256>>>();
    k_fill<<<(N_EDGES + 255) / 256, 256>>>(src, dst);

    const int spmm_blocks = (N_NODES * 32) / 256;        // 12500
    const int gemm_blocks = N_NODES / GEMM_ROWS;         // 3125

    for (int l = 0; l < 5; l++) {
        k_spmm<<<spmm_blocks, 256>>>(h, l == 0 ? 1 : 0);
        k_gemm<<<gemm_blocks, 256, GEMM_SMEM>>>(W[l], b[l]);
    }

    k_pool <<<(N_NODES + POOL_NODES - 1) / POOL_NODES, 128>>>(gid);
    k_final<<<N_GRAPHS, 128>>>(fcw, fcb, out);
}

// round 3
// speedup vs baseline: 1.3844x; 1.3844x over previous
#include <cuda_runtime.h>
#include <math.h>

#define N_NODES 100000
#define N_EDGES 1600000
#define N_GRAPHS 64
#define D 128

// ---------------- scratch (no allocations allowed) ----------------
__device__ float g_bufA[N_NODES * D];   // GEMM output / spmm input
__device__ float g_bufB[N_NODES * D];   // spmm output / GEMM input
__device__ float g_norm_src[N_NODES];
__device__ float g_norm_dst[N_NODES];
__device__ int   g_indeg[N_NODES];
__device__ int   g_outdeg[N_NODES];
__device__ int   g_rowstart[N_NODES];
__device__ int   g_cursor[N_NODES];
__device__ int   g_col[N_EDGES];
__device__ float g_gsum[N_GRAPHS * D];
__device__ int   g_gcnt[N_GRAPHS];
__device__ int   g_ctr;

// ---------------- init ----------------
__global__ void k_zero() {
    int i = blockIdx.x * blockDim.x + threadIdx.x;
    int stride = gridDim.x * blockDim.x;
    for (int j = i; j < N_NODES; j += stride) {
        g_indeg[j] = 0; g_outdeg[j] = 0; g_cursor[j] = 0;
    }
    for (int j = i; j < N_GRAPHS * D; j += stride) g_gsum[j] = 0.f;
    if (i < N_GRAPHS) g_gcnt[i] = 0;
    if (i == 0) g_ctr = 0;
}

__global__ void k_deg(const int* __restrict__ src, const int* __restrict__ dst) {
    int e = blockIdx.x * blockDim.x + threadIdx.x;
    if (e >= N_EDGES) return;
    atomicAdd(&g_outdeg[src[e]], 1);
    atomicAdd(&g_indeg[dst[e]], 1);
}

// norms + CSR row-start reservation (order-free: rows get arbitrary but
// disjoint contiguous regions -> no prefix scan needed)
__global__ void k_norm() {
    int i = blockIdx.x * blockDim.x + threadIdx.x;
    if (i >= N_NODES) return;
    int od = g_outdeg[i], id = g_indeg[i];
    g_norm_src[i] = rsqrtf((float)(od > 1 ? od : 1));
    g_norm_dst[i] = rsqrtf((float)(id > 1 ? id : 1));
    g_rowstart[i] = atomicAdd(&g_ctr, id);
}

__global__ void k_fill(const int* __restrict__ src, const int* __restrict__ dst) {
    int e = blockIdx.x * blockDim.x + threadIdx.x;
    if (e >= N_EDGES) return;
    int d = dst[e];
    int pos = atomicAdd(&g_cursor[d], 1);
    g_col[g_rowstart[d] + pos] = src[e];
}

// ---------------- SpMM: agg[i] = norm_dst[i] * sum_{e in row i} norm_src[s]*h[s]
// warp per destination row, thread = 4 features (float4), no atomics.
__global__ __launch_bounds__(256) void k_spmm(const float* __restrict__ ext, int first) {
    int gt = blockIdx.x * blockDim.x + threadIdx.x;
    int node = gt >> 5;
    int lane = gt & 31;
    if (node >= N_NODES) return;

    const float* hin = first ? ext : (const float*)g_bufA;
    const float4* __restrict__ h4 = (const float4*)hin;

    const int start = g_rowstart[node];
    const int deg   = g_indeg[node];

    float ax = 0.f, ay = 0.f, az = 0.f, aw = 0.f;
    int e = 0;
    for (; e + 4 <= deg; e += 4) {
        int s0 = g_col[start + e + 0];
        int s1 = g_col[start + e + 1];
        int s2 = g_col[start + e + 2];
        int s3 = g_col[start + e + 3];
        float c0 = g_norm_src[s0];
        float c1 = g_norm_src[s1];
        float c2 = g_norm_src[s2];
        float c3 = g_norm_src[s3];
        float4 v0 = h4[(size_t)s0 * 32 + lane];
        float4 v1 = h4[(size_t)s1 * 32 + lane];
        float4 v2 = h4[(size_t)s2 * 32 + lane];
        float4 v3 = h4[(size_t)s3 * 32 + lane];
        ax = fmaf(c0, v0.x, ax); ay = fmaf(c0, v0.y, ay);
        az = fmaf(c0, v0.z, az); aw = fmaf(c0, v0.w, aw);
        ax = fmaf(c1, v1.x, ax); ay = fmaf(c1, v1.y, ay);
        az = fmaf(c1, v1.z, az); aw = fmaf(c1, v1.w, aw);
        ax = fmaf(c2, v2.x, ax); ay = fmaf(c2, v2.y, ay);
        az = fmaf(c2, v2.z, az); aw = fmaf(c2, v2.w, aw);
        ax = fmaf(c3, v3.x, ax); ay = fmaf(c3, v3.y, ay);
        az = fmaf(c3, v3.z, az); aw = fmaf(c3, v3.w, aw);
    }
    for (; e < deg; e++) {
        int s = g_col[start + e];
        float c = g_norm_src[s];
        float4 v = h4[(size_t)s * 32 + lane];
        ax = fmaf(c, v.x, ax); ay = fmaf(c, v.y, ay);
        az = fmaf(c, v.z, az); aw = fmaf(c, v.w, aw);
    }
    float nd = g_norm_dst[node];
    float4 o;
    o.x = ax * nd; o.y = ay * nd; o.z = az * nd; o.w = aw * nd;
    ((float4*)g_bufB)[(size_t)node * 32 + lane] = o;
}

// ---------------- GEMM (tf32 tensor cores): g_bufA = g_bufB @ W + b
// Block tile: 64 rows x 128 cols x K=128. 256 threads = 8 warps (2 M x 4 N),
// warp tile 32x32 via mma.sync.m16n8k8.tf32 (2 m-tiles x 4 n-tiles).
#define BM 64
#define AS_STRIDE 132   // 128 + 4 pad -> conflict-free A fragment LDS
#define WS_STRIDE 136   // 128 + 8 pad -> conflict-free B fragment LDS
#define GEMM_SMEM ((BM * AS_STRIDE + D * WS_STRIDE) * (int)sizeof(float)) // 103424

__device__ __forceinline__ unsigned f2tf32(float x) {
    unsigned r;
    asm("cvt.rna.tf32.f32 %0, %1;" : "=r"(r) : "f"(x));
    return r;
}

__global__ __launch_bounds__(256, 2) void k_gemm(const float* __restrict__ W,
                                                 const float* __restrict__ bias) {
    extern __shared__ unsigned sm[];
    unsigned* Ws = sm;                       // D x WS_STRIDE
    unsigned* As = sm + D * WS_STRIDE;       // BM x AS_STRIDE
    int tid = threadIdx.x;
    int row0 = blockIdx.x * BM;

    // Load W (128x128) -> smem as tf32, padded stride
    const float4* W4 = (const float4*)W;
#pragma unroll
    for (int i = 0; i < 16; i++) {
        int f = tid + i * 256;               // 4096 float4
        int r = f >> 5, c4 = f & 31;
        float4 v = W4[f];
        unsigned* p = Ws + r * WS_STRIDE + c4 * 4;
        p[0] = f2tf32(v.x); p[1] = f2tf32(v.y);
        p[2] = f2tf32(v.z); p[3] = f2tf32(v.w);
    }
    // Load A tile (64x128) -> smem as tf32
    const float4* A4 = (const float4*)g_bufB;
#pragma unroll
    for (int i = 0; i < 8; i++) {
        int f = tid + i * 256;               // 2048 float4
        int r = f >> 5, c4 = f & 31;
        int grow = row0 + r;
        float4 v = (grow < N_NODES) ? A4[(size_t)grow * 32 + c4]
                                    : make_float4(0.f, 0.f, 0.f, 0.f);
        unsigned* p = As + r * AS_STRIDE + c4 * 4;
        p[0] = f2tf32(v.x); p[1] = f2tf32(v.y);
        p[2] = f2tf32(v.z); p[3] = f2tf32(v.w);
    }
    __syncthreads();

    int warp = tid >> 5, lane = tid & 31;
    int wm = (warp >> 2) * 32;               // 0 / 32
    int wn = (warp & 3) * 32;                // 0 / 32 / 64 / 96
    int qr = lane >> 2;                      // 0..7
    int qc = lane & 3;                       // 0..3

    float c[2][4][4];
#pragma unroll
    for (int mt = 0; mt < 2; mt++)
#pragma unroll
        for (int nt = 0; nt < 4; nt++)
#pragma unroll
            for (int j = 0; j < 4; j++) c[mt][nt][j] = 0.f;

#pragma unroll
    for (int ks = 0; ks < 16; ks++) {
        int k0 = ks * 8;
        unsigned a[2][4];
#pragma unroll
        for (int mt = 0; mt < 2; mt++) {
            const unsigned* base = As + (wm + mt * 16 + qr) * AS_STRIDE + k0 + qc;
            a[mt][0] = base[0];
            a[mt][2] = base[4];
            a[mt][1] = base[8 * AS_STRIDE];
            a[mt][3] = base[8 * AS_STRIDE + 4];
        }
#pragma unroll
        for (int nt = 0; nt < 4; nt++) {
            unsigned b0 = Ws[(k0 + qc) * WS_STRIDE + wn + nt * 8 + qr];
            unsigned b1 = Ws[(k0 + qc + 4) * WS_STRIDE + wn + nt * 8 + qr];
#pragma unroll
            for (int mt = 0; mt < 2; mt++) {
                asm volatile(
                    "mma.sync.aligned.m16n8k8.row.col.f32.tf32.tf32.f32 "
                    "{%0,%1,%2,%3}, {%4,%5,%6,%7}, {%8,%9}, {%0,%1,%2,%3};"
                    : "+f"(c[mt][nt][0]), "+f"(c[mt][nt][1]),
                      "+f"(c[mt][nt][2]), "+f"(c[mt][nt][3])
                    : "r"(a[mt][0]), "r"(a[mt][1]), "r"(a[mt][2]), "r"(a[mt][3]),
                      "r"(b0), "r"(b1));
            }
        }
    }

    // Epilogue: + bias, write fp32
#pragma unroll
    for (int mt = 0; mt < 2; mt++) {
        int r_lo = row0 + wm + mt * 16 + qr;
        int r_hi = r_lo + 8;
#pragma unroll
        for (int nt = 0; nt < 4; nt++) {
            int col = wn + nt * 8 + qc * 2;
            float2 bb = *(const float2*)(bias + col);
            if (r_lo < N_NODES) {
                float2 v; v.x = c[mt][nt][0] + bb.x; v.y = c[mt][nt][1] + bb.y;
                *(float2*)(g_bufA + (size_t)r_lo * D + col) = v;
            }
            if (r_hi < N_NODES) {
                float2 v; v.x = c[mt][nt][2] + bb.x; v.y = c[mt][nt][3] + bb.y;
                *(float2*)(g_bufA + (size_t)r_hi * D + col) = v;
            }
        }
    }
}

// ---------------- mean-pool (graph_ids sorted -> segmented run-length reduce)
#define POOL_NODES 256
__global__ __launch_bounds__(128) void k_pool(const int* __restrict__ gid) {
    __shared__ int sg[POOL_NODES];
    int base = blockIdx.x * POOL_NODES;
    int tid = threadIdx.x;   // feature index, 128 threads
    for (int i = tid; i < POOL_NODES; i += 128) {
        int n = base + i;
        sg[i] = (n < N_NODES) ? gid[n] : -1;
    }
    __syncthreads();
    int nn = N_NODES - base; if (nn > POOL_NODES) nn = POOL_NODES;
    const float* h = (const float*)g_bufA;

    float acc = 0.f;
    int cur = sg[0];
    int run = 0;
    for (int i = 0; i < nn; i++) {
        int g = sg[i];
        if (g != cur) {
            atomicAdd(&g_gsum[cur * D + tid], acc);
            if (tid == 0) atomicAdd(&g_gcnt[cur], run);
            acc = 0.f; run = 0; cur = g;
        }
        acc += h[(size_t)(base + i) * D + tid];
        run++;
    }
    atomicAdd(&g_gsum[cur * D + tid], acc);
    if (tid == 0) atomicAdd(&g_gcnt[cur], run);
}

// ---------------- head: sigmoid(mean @ fc_w^T + fc_b)
__global__ __launch_bounds__(128) void k_final(const float* __restrict__ fcw,
                                               const float* __restrict__ fcb,
                                               float* __restrict__ out) {
    __shared__ float red[128];
    int g = blockIdx.x;
    int tid = threadIdx.x;
    red[tid] = g_gsum[g * D + tid] * fcw[tid];
    __syncthreads();
#pragma unroll
    for (int s = 64; s > 0; s >>= 1) {
        if (tid < s) red[tid] += red[tid + s];
        __syncthreads();
    }
    if (tid == 0) {
        int c = g_gcnt[g]; if (c < 1) c = 1;
        float x = red[0] / (float)c + fcb[0];
        out[g] = 1.f / (1.f + expf(-x));
    }
}

// ---------------- launch ----------------
extern "C" void kernel_launch(void* const* d_in, const int* in_sizes, int n_in,
                              void* d_out, int out_size) {
    const float* h    = (const float*)d_in[0];
    const int*   src  = (const int*)  d_in[1];
    const int*   dst  = (const int*)  d_in[2];
    const int*   gid  = (const int*)  d_in[3];
    const float* W[5] = {(const float*)d_in[4],  (const float*)d_in[6],
                         (const float*)d_in[8],  (const float*)d_in[10],
                         (const float*)d_in[12]};
    const float* b[5] = {(const float*)d_in[5],  (const float*)d_in[7],
                         (const float*)d_in[9],  (const float*)d_in[11],
                         (const float*)d_in[13]};
    const float* fcw  = (const float*)d_in[14];
    const float* fcb  = (const float*)d_in[15];
    float* out = (float*)d_out;

    cudaFuncSetAttribute(k_gemm, cudaFuncAttributeMaxDynamicSharedMemorySize, GEMM_SMEM);

    k_zero<<<256, 256>>>();
    k_deg <<<(N_EDGES + 255) / 256, 256>>>(src, dst);
    k_norm<<<(N_NODES + 255) / 256, 256>>>();
    k_fill<<<(N_EDGES + 255) / 256, 256>>>(src, dst);

    const int spmm_blocks = (N_NODES * 32) / 256;          // 12500
    const int gemm_blocks = (N_NODES + BM - 1) / BM;       // 1563

    for (int l = 0; l < 5; l++) {
        k_spmm<<<spmm_blocks, 256>>>(h, l == 0 ? 1 : 0);
        k_gemm<<<gemm_blocks, 256, GEMM_SMEM>>>(W[l], b[l]);
    }

    k_pool <<<(N_NODES + POOL_NODES - 1) / POOL_NODES, 128>>>(gid);
    k_final<<<N_GRAPHS, 128>>>(fcw, fcb, out);
}